// round 1
// baseline (speedup 1.0000x reference)
#include <cuda_runtime.h>
#include <cstdint>
#include <cstdio>

#define B_  16
#define NC_ 10
#define H_  6
#define C_  384
#define HD_ 64
#define T_  197
#define N_  196
#define BH_ (B_*H_)    // 96
#define CH_ (NC_*H_)   // 60
#define SCALE_ 0.125f

// ---------------- scratch (static device memory; no allocations) ----------------
__device__ float g_n1 [26*C_];
__device__ float g_n2x[B_*N_*C_];
__device__ float g_n2a[NC_*N_*C_];
__device__ float g_q  [NC_*C_];
__device__ float g_v  [NC_*C_];
__device__ float g_k  [B_*C_];
__device__ float g_attn[B_*CH_];   // attn_cls [b][n][h] flat; also w2 [b][h][c] flat
__device__ float g_ctx[B_*C_];
__device__ float g_qh [BH_*N_*HD_];
__device__ float g_q2 [BH_*N_*HD_];
__device__ float g_vr [BH_*N_*HD_];
__device__ float g_kh [CH_*N_*HD_];
__device__ float g_k2 [CH_*N_*HD_];
__device__ float g_tmp[BH_*N_*N_];        // 14.7 MB
__device__ float g_rectH[B_*N_*C_];       // == rect.reshape(B,N,C), contiguous
__device__ float g_xx [B_*T_*C_];
__device__ float g_hdn[B_*T_*C_];
__device__ float g_h1 [B_*T_*4*C_];       // 19.4 MB

// ---------------- LayerNorm: one block per row, 128 threads ----------------
__global__ void ln_kernel(const float* __restrict__ in, float* __restrict__ out,
                          const float* __restrict__ g, const float* __restrict__ bt,
                          int rows, int inner, long outer_stride, long inner_stride)
{
    int row = blockIdx.x;
    if (row >= rows) return;
    const float* src = in + (long)(row / inner) * outer_stride + (long)(row % inner) * inner_stride;
    int t = threadIdx.x;
    float v[3]; float s = 0.f;
#pragma unroll
    for (int i = 0; i < 3; i++) { v[i] = src[t + i*128]; s += v[i]; }
    __shared__ float red[4];
#pragma unroll
    for (int o = 16; o > 0; o >>= 1) s += __shfl_xor_sync(0xffffffffu, s, o);
    if ((t & 31) == 0) red[t >> 5] = s;
    __syncthreads();
    float mean = (red[0] + red[1] + red[2] + red[3]) * (1.f/384.f);
    float q = 0.f;
#pragma unroll
    for (int i = 0; i < 3; i++) { float d = v[i] - mean; q += d*d; }
#pragma unroll
    for (int o = 16; o > 0; o >>= 1) q += __shfl_xor_sync(0xffffffffu, q, o);
    __syncthreads();
    if ((t & 31) == 0) red[t >> 5] = q;
    __syncthreads();
    float var = (red[0] + red[1] + red[2] + red[3]) * (1.f/384.f);
    float rs = rsqrtf(var + 1e-5f);
    float* dst = out + (long)row * C_;
#pragma unroll
    for (int i = 0; i < 3; i++) { int c = t + i*128; dst[c] = (v[i] - mean) * rs * g[c] + bt[c]; }
}

// ---------------- cls path: q,v (anchors) and k (samples) ----------------
__global__ void cls_qvk_kernel(const float* __restrict__ n1, const float* __restrict__ Wqv,
                               const float* __restrict__ Wk,
                               float* __restrict__ q, float* __restrict__ v, float* __restrict__ k)
{
    __shared__ float row[C_];
    int bid = blockIdx.x, t = threadIdx.x; // 256 threads
    const float* src; const float* W; int ncols;
    if (bid < NC_) { src = n1 + (16 + bid)*C_; W = Wqv; ncols = 2*C_; }
    else           { src = n1 + (bid - NC_)*C_; W = Wk;  ncols = C_; }
    for (int i = t; i < C_; i += 256) row[i] = src[i];
    __syncthreads();
    for (int col = t; col < ncols; col += 256) {
        float s = 0.f;
        for (int kk = 0; kk < C_; kk++) s += row[kk] * W[(size_t)kk*ncols + col];
        if (bid < NC_) { if (col < C_) q[bid*C_ + col] = s; else v[bid*C_ + col - C_] = s; }
        else k[(bid - NC_)*C_ + col] = s;
    }
}

// ---------------- cls attention: softmax over anchors + ctx ----------------
__global__ void attn_cls_kernel(const float* __restrict__ q, const float* __restrict__ k,
                                const float* __restrict__ v,
                                float* __restrict__ attn, float* __restrict__ ctx)
{
    int b = blockIdx.x, t = threadIdx.x; // 384 threads
    __shared__ float sl[CH_];
    if (t < CH_) {
        int n = t / H_, h = t % H_;
        float s = 0.f;
        for (int d = 0; d < HD_; d++) s += q[n*C_ + h*HD_ + d] * k[b*C_ + h*HD_ + d];
        sl[t] = s * SCALE_;
    }
    __syncthreads();
    if (t < H_) {
        float mx = -1e30f;
        for (int n = 0; n < NC_; n++) mx = fmaxf(mx, sl[n*H_ + t]);
        float sum = 0.f;
        for (int n = 0; n < NC_; n++) { float e = expf(sl[n*H_ + t] - mx); sl[n*H_ + t] = e; sum += e; }
        float inv = 1.f / sum;
        for (int n = 0; n < NC_; n++) { sl[n*H_ + t] *= inv; attn[b*CH_ + n*H_ + t] = sl[n*H_ + t]; }
    }
    __syncthreads();
    {
        int h = t >> 6, d = t & 63;
        float s = 0.f;
        for (int n = 0; n < NC_; n++) s += sl[n*H_ + h] * v[n*C_ + h*HD_ + d];
        ctx[b*C_ + t] = s;
    }
}

// ---------------- cls projection into xx row 0 ----------------
__global__ void cls_proj_kernel(const float* __restrict__ ctx, const float* __restrict__ W,
                                const float* __restrict__ bias, float* __restrict__ xx)
{
    int b = blockIdx.x, t = threadIdx.x; // 384 threads
    __shared__ float row[C_];
    row[t] = ctx[b*C_ + t];
    __syncthreads();
    float s = bias[t];
    for (int kk = 0; kk < C_; kk++) s += row[kk] * W[kk*C_ + t];
    xx[(size_t)b*T_*C_ + t] = s;
}

// ---------------- generic tiled SGEMM: C = act(A@W + bias) (+res) -----------
// mode 0: plain row-major (ld=N)
// mode 1: head-major: [(b*6 + nn/64)*196 + mm%196]*64 + nn%64, b=mm/196
// mode 2: xx rows: [(mm/196)*197 + 1 + mm%196]*384 + nn
__device__ __forceinline__ size_t out_map(int mode, int mm, int nn, int N)
{
    if (mode == 0) return (size_t)mm * N + nn;
    if (mode == 1) {
        int bq = mm / N_, n = mm % N_;
        return ((size_t)(bq*H_ + (nn >> 6)) * N_ + n) * HD_ + (nn & 63);
    }
    int bq = mm / N_, n = mm % N_;
    return ((size_t)bq*T_ + 1 + n) * C_ + nn;
}
__device__ __forceinline__ float gelu_f(float x) {
    return 0.5f * x * (1.f + erff(x * 0.7071067811865475f));
}

__global__ __launch_bounds__(256)
void gemm_kernel(const float* __restrict__ A, const float* __restrict__ W,
                 const float* __restrict__ bias, const float* __restrict__ res,
                 float* __restrict__ C, int M, int N, int K, int act, int mode)
{
    __shared__ float As[16][68];
    __shared__ float Bs[16][68];
    int m0 = blockIdx.y * 64, n0 = blockIdx.x * 64;
    int tid = threadIdx.x;
    int tx = tid & 15, ty = tid >> 4;
    int arow = tid >> 2, akq = tid & 3;
    int brow = tid >> 4, bnq = tid & 15;
    float acc[4][4];
#pragma unroll
    for (int i = 0; i < 4; i++)
#pragma unroll
        for (int j = 0; j < 4; j++) acc[i][j] = 0.f;

    for (int kk0 = 0; kk0 < K; kk0 += 16) {
        float4 av = make_float4(0.f,0.f,0.f,0.f);
        if (m0 + arow < M) av = *(const float4*)(A + (size_t)(m0 + arow)*K + kk0 + akq*4);
        float4 bv = *(const float4*)(W + (size_t)(kk0 + brow)*N + n0 + bnq*4);
        __syncthreads();
        As[akq*4+0][arow] = av.x; As[akq*4+1][arow] = av.y;
        As[akq*4+2][arow] = av.z; As[akq*4+3][arow] = av.w;
        *(float4*)(&Bs[brow][bnq*4]) = bv;
        __syncthreads();
#pragma unroll
        for (int kk = 0; kk < 16; kk++) {
            float4 a  = *(const float4*)(&As[kk][ty*4]);
            float4 bb = *(const float4*)(&Bs[kk][tx*4]);
            acc[0][0] += a.x*bb.x; acc[0][1] += a.x*bb.y; acc[0][2] += a.x*bb.z; acc[0][3] += a.x*bb.w;
            acc[1][0] += a.y*bb.x; acc[1][1] += a.y*bb.y; acc[1][2] += a.y*bb.z; acc[1][3] += a.y*bb.w;
            acc[2][0] += a.z*bb.x; acc[2][1] += a.z*bb.y; acc[2][2] += a.z*bb.z; acc[2][3] += a.z*bb.w;
            acc[3][0] += a.w*bb.x; acc[3][1] += a.w*bb.y; acc[3][2] += a.w*bb.z; acc[3][3] += a.w*bb.w;
        }
    }
#pragma unroll
    for (int i = 0; i < 4; i++) {
        int mm = m0 + ty*4 + i;
        if (mm >= M) continue;
#pragma unroll
        for (int j = 0; j < 4; j++) {
            int nn = n0 + tx*4 + j;
            float val = acc[i][j];
            if (bias) val += bias[nn];
            if (act) val = gelu_f(val);
            size_t idx = out_map(mode, mm, nn, N);
            if (res) val += res[idx];
            C[idx] = val;
        }
    }
}

// ---------------- fused rectified attention core -> tmp ----------------
// tmp[b,h,n,k] = sum_c w2[b,h,c] * sum_m relu(-S*qh_n.kh_m) * relu(S*k2_m.q2_k)
__global__ __launch_bounds__(256)
void fused_attn_kernel(const float* __restrict__ qh, const float* __restrict__ kh,
                       const float* __restrict__ q2, const float* __restrict__ k2,
                       const float* __restrict__ w2all, float* __restrict__ tmp_out)
{
    extern __shared__ float sm[];
    float* qh_s = sm;               // [112][64]
    float* q2_s = qh_s + 112*64;    // [112][64]
    float* kh_s = q2_s + 112*64;    // [16][64]
    float* k2_s = kh_s + 16*64;     // [16][64]
    float* L_s  = k2_s + 16*64;     // [16][112]  (w2-scaled)
    float* R_s  = L_s  + 16*112;    // [16][112]

    int bh = blockIdx.z;
    int b = bh / H_, h = bh % H_;
    int n0 = blockIdx.y * 112;
    int k0 = blockIdx.x * 112;
    int tid = threadIdx.x;
    int tx = tid & 15, ty = tid >> 4;

    const float* qh_b = qh + (size_t)bh * N_ * HD_;
    const float* q2_b = q2 + (size_t)bh * N_ * HD_;

    for (int i = tid; i < 112*16; i += 256) {
        int r = i >> 4, dq = i & 15;
        int n = n0 + r;
        float4 a = (n < N_) ? *(const float4*)(qh_b + (size_t)n*HD_ + dq*4) : make_float4(0,0,0,0);
        *(float4*)(qh_s + r*64 + dq*4) = a;
        int kk = k0 + r;
        float4 u = (kk < N_) ? *(const float4*)(q2_b + (size_t)kk*HD_ + dq*4) : make_float4(0,0,0,0);
        *(float4*)(q2_s + r*64 + dq*4) = u;
    }

    float acc[7][7];
#pragma unroll
    for (int i = 0; i < 7; i++)
#pragma unroll
        for (int j = 0; j < 7; j++) acc[i][j] = 0.f;

    for (int c = 0; c < NC_; c++) {
        float w = w2all[b*CH_ + h*NC_ + c];
        const float* kh_c = kh + (size_t)(c*H_ + h) * N_ * HD_;
        const float* k2_c = k2 + (size_t)(c*H_ + h) * N_ * HD_;
        for (int m0 = 0; m0 < N_; m0 += 16) {
            __syncthreads();
            {
                int r = tid >> 4, dq = tid & 15;
                int m = m0 + r;
                float4 a = (m < N_) ? *(const float4*)(kh_c + (size_t)m*HD_ + dq*4) : make_float4(0,0,0,0);
                *(float4*)(kh_s + r*64 + dq*4) = a;
                float4 u = (m < N_) ? *(const float4*)(k2_c + (size_t)m*HD_ + dq*4) : make_float4(0,0,0,0);
                *(float4*)(k2_s + r*64 + dq*4) = u;
            }
            __syncthreads();
            {
                float la[7], ra[7];
#pragma unroll
                for (int i = 0; i < 7; i++) { la[i] = 0.f; ra[i] = 0.f; }
                const float4* khv = (const float4*)(kh_s + tx*64);
                const float4* k2v = (const float4*)(k2_s + tx*64);
#pragma unroll
                for (int dq = 0; dq < 16; dq++) {
                    float4 kv  = khv[dq];
                    float4 k2x = k2v[dq];
#pragma unroll
                    for (int i = 0; i < 7; i++) {
                        float4 qv  = *(const float4*)(qh_s + (ty*7 + i)*64 + dq*4);
                        la[i] += qv.x*kv.x + qv.y*kv.y + qv.z*kv.z + qv.w*kv.w;
                        float4 q2x = *(const float4*)(q2_s + (ty*7 + i)*64 + dq*4);
                        ra[i] += q2x.x*k2x.x + q2x.y*k2x.y + q2x.z*k2x.z + q2x.w*k2x.w;
                    }
                }
#pragma unroll
                for (int i = 0; i < 7; i++) {
                    L_s[tx*112 + ty*7 + i] = w * fmaxf(0.f, -SCALE_ * la[i]);
                    R_s[tx*112 + ty*7 + i] = fmaxf(0.f, SCALE_ * ra[i]);
                }
            }
            __syncthreads();
#pragma unroll 4
            for (int m = 0; m < 16; m++) {
                float lv[7], rv[7];
#pragma unroll
                for (int i = 0; i < 7; i++) lv[i] = L_s[m*112 + ty*7 + i];
#pragma unroll
                for (int j = 0; j < 7; j++) rv[j] = R_s[m*112 + tx*7 + j];
#pragma unroll
                for (int i = 0; i < 7; i++)
#pragma unroll
                    for (int j = 0; j < 7; j++) acc[i][j] += lv[i]*rv[j];
            }
        }
    }

    float* outp = tmp_out + (size_t)bh * N_ * N_;
#pragma unroll
    for (int i = 0; i < 7; i++) {
        int n = n0 + ty*7 + i;
        if (n >= N_) continue;
#pragma unroll
        for (int j = 0; j < 7; j++) {
            int kk = k0 + tx*7 + j;
            if (kk < N_) outp[(size_t)n*N_ + kk] = acc[i][j];
        }
    }
}

// ---------------- rect = tmp @ vr (per b,h) -> rectH (== reshaped) ----------
__global__ __launch_bounds__(256)
void rect_kernel(const float* __restrict__ tmp, const float* __restrict__ vr,
                 float* __restrict__ rectH)
{
    extern __shared__ float sm[];
    float* vr_s  = sm;            // [196][64]
    float* tmp_s = sm + N_*HD_;   // [4][196]
    int bh = blockIdx.y;
    int r0 = blockIdx.x * 4;
    const float* vrb = vr + (size_t)bh * N_ * HD_;
    for (int i = threadIdx.x; i < N_*HD_/4; i += 256)
        ((float4*)vr_s)[i] = ((const float4*)vrb)[i];
    const float* tb = tmp + (size_t)bh * N_ * N_;
    for (int i = threadIdx.x; i < 4*N_; i += 256) {
        int rr = i / N_, kk = i % N_;
        tmp_s[i] = tb[(size_t)(r0 + rr)*N_ + kk];
    }
    __syncthreads();
    int d = threadIdx.x & 63, rr = threadIdx.x >> 6;
    float a = 0.f;
    for (int kk = 0; kk < N_; kk++) a += tmp_s[rr*N_ + kk] * vr_s[kk*HD_ + d];
    rectH[(size_t)bh*N_*HD_ + (size_t)(r0 + rr)*HD_ + d] = a;
}

// ---------------- anchor copy ----------------
__global__ void copy_kernel(const float* __restrict__ src, float* __restrict__ dst, int n4)
{
    int i = blockIdx.x * blockDim.x + threadIdx.x;
    if (i < n4) ((float4*)dst)[i] = ((const float4*)src)[i];
}

// ---------------- launch ----------------
extern "C" void kernel_launch(void* const* d_in, const int* in_sizes, int n_in,
                              void* d_out, int out_size)
{
    const float* x       = (const float*)d_in[0];
    const float* Wqv     = (const float*)d_in[1];
    const float* Wk      = (const float*)d_in[2];
    const float* Wq_proj = (const float*)d_in[3];
    const float* bq_proj = (const float*)d_in[4];
    const float* Wqk     = (const float*)d_in[5];
    const float* Wqk2    = (const float*)d_in[6];
    const float* Wv      = (const float*)d_in[7];
    const float* Wr_proj = (const float*)d_in[8];
    const float* br_proj = (const float*)d_in[9];
    const float* g1      = (const float*)d_in[10];
    const float* b1      = (const float*)d_in[11];
    const float* g2      = (const float*)d_in[12];
    const float* b2      = (const float*)d_in[13];
    const float* g3      = (const float*)d_in[14];
    const float* b3      = (const float*)d_in[15];
    const float* W1      = (const float*)d_in[16];
    const float* bm1     = (const float*)d_in[17];
    const float* W2      = (const float*)d_in[18];
    const float* bm2     = (const float*)d_in[19];
    float* outp = (float*)d_out;

    float *n1, *n2x, *n2a, *qb, *vb, *kb, *attn, *ctx, *qh, *q2, *vrp, *khp, *k2p;
    float *tmp, *rectH, *xx, *hdn, *h1;
    cudaGetSymbolAddress((void**)&n1, g_n1);
    cudaGetSymbolAddress((void**)&n2x, g_n2x);
    cudaGetSymbolAddress((void**)&n2a, g_n2a);
    cudaGetSymbolAddress((void**)&qb, g_q);
    cudaGetSymbolAddress((void**)&vb, g_v);
    cudaGetSymbolAddress((void**)&kb, g_k);
    cudaGetSymbolAddress((void**)&attn, g_attn);
    cudaGetSymbolAddress((void**)&ctx, g_ctx);
    cudaGetSymbolAddress((void**)&qh, g_qh);
    cudaGetSymbolAddress((void**)&q2, g_q2);
    cudaGetSymbolAddress((void**)&vrp, g_vr);
    cudaGetSymbolAddress((void**)&khp, g_kh);
    cudaGetSymbolAddress((void**)&k2p, g_k2);
    cudaGetSymbolAddress((void**)&tmp, g_tmp);
    cudaGetSymbolAddress((void**)&rectH, g_rectH);
    cudaGetSymbolAddress((void**)&xx, g_xx);
    cudaGetSymbolAddress((void**)&hdn, g_hdn);
    cudaGetSymbolAddress((void**)&h1, g_h1);

    const int SMEM_F = 19968 * 4;        // fused attention
    const int SMEM_R = (N_*HD_ + 4*N_) * 4; // rect
    cudaFuncSetAttribute(fused_attn_kernel, cudaFuncAttributeMaxDynamicSharedMemorySize, SMEM_F);
    cudaFuncSetAttribute(rect_kernel, cudaFuncAttributeMaxDynamicSharedMemorySize, SMEM_R);

    // 1) LayerNorms on cls tokens and image tokens
    ln_kernel<<<26, 128>>>(x, n1, g1, b1, 26, 26, 0, (long)T_*C_);
    ln_kernel<<<B_*N_, 128>>>(x + C_, n2x, g2, b2, B_*N_, N_, (long)T_*C_, C_);
    ln_kernel<<<NC_*N_, 128>>>(x + (long)16*T_*C_ + C_, n2a, g2, b2, NC_*N_, N_, (long)T_*C_, C_);

    // 2) cls path
    cls_qvk_kernel<<<26, 256>>>(n1, Wqv, Wk, qb, vb, kb);
    attn_cls_kernel<<<B_, 384>>>(qb, kb, vb, attn, ctx);
    cls_proj_kernel<<<B_, 384>>>(ctx, Wq_proj, bq_proj, xx);

    // 3) head projections (head-major outputs)
    dim3 gx(6, 49), ga(6, 31);
    gemm_kernel<<<gx, 256>>>(n2x, Wqk,  nullptr, nullptr, qh,  B_*N_, C_, C_, 0, 1);
    gemm_kernel<<<gx, 256>>>(n2x, Wqk2, nullptr, nullptr, q2,  B_*N_, C_, C_, 0, 1);
    gemm_kernel<<<gx, 256>>>(n2x, Wv,   nullptr, nullptr, vrp, B_*N_, C_, C_, 0, 1);
    gemm_kernel<<<ga, 256>>>(n2a, Wqk,  nullptr, nullptr, khp, NC_*N_, C_, C_, 0, 1);
    gemm_kernel<<<ga, 256>>>(n2a, Wqk2, nullptr, nullptr, k2p, NC_*N_, C_, C_, 0, 1);

    // 4) fused rectified attention core
    dim3 gf(2, 2, BH_);
    fused_attn_kernel<<<gf, 256, SMEM_F>>>(qh, khp, q2, k2p, attn, tmp);

    // 5) rect = tmp @ vr  (rectH is already the reshaped (B,N,C) matrix)
    dim3 gr(49, BH_);
    rect_kernel<<<gr, 256, SMEM_R>>>(tmp, vrp, rectH);

    // 6) rect projection + x_im residual -> xx rows 1..196
    gemm_kernel<<<gx, 256>>>(rectH, Wr_proj, br_proj, x, xx, B_*N_, C_, C_, 0, 2);

    // 7) MLP with LN3, exact GELU, residual; write batches 0..15 of output
    ln_kernel<<<B_*T_, 128>>>(xx, hdn, g3, b3, B_*T_, B_*T_, 0, C_);
    dim3 gm1(24, 50), gm2(6, 50);
    gemm_kernel<<<gm1, 256>>>(hdn, W1, bm1, nullptr, h1, B_*T_, 4*C_, C_, 1, 0);
    gemm_kernel<<<gm2, 256>>>(h1, W2, bm2, xx, outp, B_*T_, C_, 4*C_, 0, 0);

    // 8) anchors pass through unchanged
    int n4 = NC_*T_*C_/4;
    copy_kernel<<<(n4 + 255)/256, 256>>>(x + (long)16*T_*C_, outp + (long)16*T_*C_, n4);
}

// round 2
// speedup vs baseline: 3.4798x; 3.4798x over previous
#include <cuda_runtime.h>
#include <cstdint>

#define B_  16
#define NC_ 10
#define H_  6
#define C_  384
#define HD_ 64
#define T_  197
#define N_  196
#define BH_ (B_*H_)    // 96
#define CH_ (NC_*H_)   // 60
#define SCALE_ 0.125f

// ---------------- scratch ----------------
__device__ float g_n1 [26*C_];
__device__ float g_n2x[B_*N_*C_];
__device__ float g_n2a[NC_*N_*C_];
__device__ float g_qv [NC_*2*C_];
__device__ float g_k  [B_*C_];
__device__ float g_attn[B_*CH_];
__device__ float g_ctx[B_*C_];
__device__ float g_qh [BH_*N_*HD_];
__device__ float g_q2 [BH_*N_*HD_];
__device__ float g_vr [BH_*N_*HD_];
__device__ float g_kh [CH_*N_*HD_];
__device__ float g_k2 [CH_*N_*HD_];
__device__ float g_tmp[BH_*N_*N_];
__device__ float g_rectH[B_*N_*C_];
__device__ float g_xx [B_*T_*C_];
__device__ float g_hdn[B_*T_*C_];
__device__ float g_h1 [B_*T_*4*C_];

// ---------------- helpers ----------------
__device__ __forceinline__ float to_tf32(float x) {
    uint32_t u;
    asm("cvt.rna.tf32.f32 %0, %1;" : "=r"(u) : "f"(x));
    return __uint_as_float(u);
}
#define U32(x) __float_as_uint(x)

__device__ __forceinline__ void mma8(float* c, uint32_t a0, uint32_t a1, uint32_t a2, uint32_t a3,
                                     uint32_t b0, uint32_t b1)
{
    asm volatile("mma.sync.aligned.m16n8k8.row.col.f32.tf32.tf32.f32 "
                 "{%0,%1,%2,%3},{%4,%5,%6,%7},{%8,%9},{%0,%1,%2,%3};\n"
                 : "+f"(c[0]), "+f"(c[1]), "+f"(c[2]), "+f"(c[3])
                 : "r"(a0), "r"(a1), "r"(a2), "r"(a3), "r"(b0), "r"(b1));
}

__device__ __forceinline__ float gelu_f(float x) {
    return 0.5f * x * (1.f + erff(x * 0.7071067811865475f));
}

// ---------------- LayerNorm ----------------
__global__ void ln_kernel(const float* __restrict__ in, float* __restrict__ out,
                          const float* __restrict__ g, const float* __restrict__ bt,
                          int rows, int inner, long outer_stride, long inner_stride)
{
    int row = blockIdx.x;
    if (row >= rows) return;
    const float* src = in + (long)(row / inner) * outer_stride + (long)(row % inner) * inner_stride;
    int t = threadIdx.x;
    float v[3]; float s = 0.f;
#pragma unroll
    for (int i = 0; i < 3; i++) { v[i] = src[t + i*128]; s += v[i]; }
    __shared__ float red[4];
#pragma unroll
    for (int o = 16; o > 0; o >>= 1) s += __shfl_xor_sync(0xffffffffu, s, o);
    if ((t & 31) == 0) red[t >> 5] = s;
    __syncthreads();
    float mean = (red[0] + red[1] + red[2] + red[3]) * (1.f/384.f);
    float q = 0.f;
#pragma unroll
    for (int i = 0; i < 3; i++) { float d = v[i] - mean; q += d*d; }
#pragma unroll
    for (int o = 16; o > 0; o >>= 1) q += __shfl_xor_sync(0xffffffffu, q, o);
    __syncthreads();
    if ((t & 31) == 0) red[t >> 5] = q;
    __syncthreads();
    float var = (red[0] + red[1] + red[2] + red[3]) * (1.f/384.f);
    float rs = rsqrtf(var + 1e-5f);
    float* dst = out + (long)row * C_;
#pragma unroll
    for (int i = 0; i < 3; i++) { int c = t + i*128; dst[c] = (v[i] - mean) * rs * g[c] + bt[c]; }
}

// ---------------- cls attention ----------------
__global__ void attn_cls_kernel(const float* __restrict__ qv, const float* __restrict__ k,
                                float* __restrict__ attn, float* __restrict__ ctx)
{
    int b = blockIdx.x, t = threadIdx.x; // 384 threads
    __shared__ float sl[CH_];
    if (t < CH_) {
        int n = t / H_, h = t % H_;
        float s = 0.f;
        for (int d = 0; d < HD_; d++) s += qv[n*2*C_ + h*HD_ + d] * k[b*C_ + h*HD_ + d];
        sl[t] = s * SCALE_;
    }
    __syncthreads();
    if (t < H_) {
        float mx = -1e30f;
        for (int n = 0; n < NC_; n++) mx = fmaxf(mx, sl[n*H_ + t]);
        float sum = 0.f;
        for (int n = 0; n < NC_; n++) { float e = expf(sl[n*H_ + t] - mx); sl[n*H_ + t] = e; sum += e; }
        float inv = 1.f / sum;
        for (int n = 0; n < NC_; n++) { sl[n*H_ + t] *= inv; attn[b*CH_ + n*H_ + t] = sl[n*H_ + t]; }
    }
    __syncthreads();
    {
        int h = t >> 6, d = t & 63;
        float s = 0.f;
        for (int n = 0; n < NC_; n++) s += sl[n*H_ + h] * qv[n*2*C_ + C_ + h*HD_ + d];
        ctx[b*C_ + t] = s;
    }
}

// ---------------- output index mapping ----------------
// mode 0: plain row-major; mode 1: head-major; mode 2: xx rows 1..196; mode 3: xx row 0
__device__ __forceinline__ size_t out_map(int mode, int mm, int nn, int N)
{
    if (mode == 0) return (size_t)mm * N + nn;
    if (mode == 1) {
        int bq = mm / N_, n = mm % N_;
        return ((size_t)(bq*H_ + (nn >> 6)) * N_ + n) * HD_ + (nn & 63);
    }
    if (mode == 2) {
        int bq = mm / N_, n = mm % N_;
        return ((size_t)bq*T_ + 1 + n) * C_ + nn;
    }
    return (size_t)mm * T_ * C_ + nn; // mode 3
}

// ---------------- tf32 GEMM: out = act(A@W + bias) (+res), mapped ----------------
__global__ __launch_bounds__(256)
void gemm_tf32(const float* __restrict__ A, const float* __restrict__ W,
               const float* __restrict__ bias, const float* __restrict__ res,
               float* __restrict__ out, int M, int N, int K, int act, int mode)
{
    __shared__ float As[16*136];
    __shared__ float Bs[16*72];
    int tid = threadIdx.x;
    int lane = tid & 31, warp = tid >> 5;
    int gid = lane >> 2, tig = lane & 3;
    int wm = warp >> 1, wn = warp & 1;            // 4 x 2 warp grid, warp tile 32x32
    int m0 = blockIdx.y * 128, n0 = blockIdx.x * 64;

    int arow = tid & 63, akq = tid >> 6;
    int brow = tid >> 4, bcol = (tid & 15) * 4;

    float acc[2][4][4];
#pragma unroll
    for (int t = 0; t < 2; t++)
#pragma unroll
        for (int u = 0; u < 4; u++)
#pragma unroll
            for (int e = 0; e < 4; e++) acc[t][u][e] = 0.f;

    for (int kk0 = 0; kk0 < K; kk0 += 16) {
        __syncthreads();
#pragma unroll
        for (int i = 0; i < 2; i++) {
            int row = arow + i*64;
            float4 v = make_float4(0.f,0.f,0.f,0.f);
            if (m0 + row < M) v = *(const float4*)(A + (size_t)(m0+row)*K + kk0 + akq*4);
            As[(akq*4+0)*136 + row] = to_tf32(v.x);
            As[(akq*4+1)*136 + row] = to_tf32(v.y);
            As[(akq*4+2)*136 + row] = to_tf32(v.z);
            As[(akq*4+3)*136 + row] = to_tf32(v.w);
        }
        {
            float4 v = *(const float4*)(W + (size_t)(kk0+brow)*N + n0 + bcol);
            float4 c = make_float4(to_tf32(v.x), to_tf32(v.y), to_tf32(v.z), to_tf32(v.w));
            *(float4*)(Bs + brow*72 + bcol) = c;
        }
        __syncthreads();
#pragma unroll
        for (int ks = 0; ks < 2; ks++) {
            int k = ks*8;
            uint32_t a[2][4];
#pragma unroll
            for (int t = 0; t < 2; t++) {
                int mb = wm*32 + t*16;
                a[t][0] = U32(As[(k+tig)*136 + mb+gid]);
                a[t][1] = U32(As[(k+tig)*136 + mb+gid+8]);
                a[t][2] = U32(As[(k+tig+4)*136 + mb+gid]);
                a[t][3] = U32(As[(k+tig+4)*136 + mb+gid+8]);
            }
#pragma unroll
            for (int u = 0; u < 4; u++) {
                int cb = wn*32 + u*8;
                uint32_t b0 = U32(Bs[(k+tig)*72 + cb+gid]);
                uint32_t b1 = U32(Bs[(k+tig+4)*72 + cb+gid]);
                mma8(acc[0][u], a[0][0],a[0][1],a[0][2],a[0][3], b0,b1);
                mma8(acc[1][u], a[1][0],a[1][1],a[1][2],a[1][3], b0,b1);
            }
        }
    }
#pragma unroll
    for (int t = 0; t < 2; t++) {
#pragma unroll
        for (int u = 0; u < 4; u++) {
            int rb = m0 + wm*32 + t*16 + gid;
            int cb = n0 + wn*32 + u*8 + 2*tig;
#pragma unroll
            for (int e = 0; e < 4; e++) {
                int r = rb + (e >> 1) * 8;
                int c = cb + (e & 1);
                if (r < M) {
                    float v = acc[t][u][e];
                    if (bias) v += bias[c];
                    if (act) v = gelu_f(v);
                    size_t idx = out_map(mode, r, c, N);
                    if (res) v += res[idx];
                    out[idx] = v;
                }
            }
        }
    }
}

// ---------------- fused rectified attention core (tf32 mma) ----------------
// tmp[bh,n,p] = sum_c w2[b,h,c] * sum_m relu(-S*qh_n.kh_m) * relu(S*k2_m.q2_p)
__global__ __launch_bounds__(256)
void fused_attn_tf32(const float* __restrict__ qh, const float* __restrict__ kh,
                     const float* __restrict__ q2, const float* __restrict__ k2,
                     const float* __restrict__ w2all, float* __restrict__ tmp_out)
{
    extern __shared__ float sm[];
    float* qh_s = sm;            // [64][136]  (d-major, n-local cols 0..127)
    float* q2t  = sm + 8704;     // [64][136]  (d-major, p-local)
    float* kht  = sm + 17408;    // [64][24]   (d-major, m 0..15)
    float* k2t  = sm + 18944;    // [64][24]
    float* L_s  = sm + 20480;    // [16][136]  (m-major, n-local)
    float* R_s  = sm + 22656;    // [16][136]  (m-major, p-local)

    int tid = threadIdx.x;
    int lane = tid & 31, warp = tid >> 5;
    int gid = lane >> 2, tig = lane & 3;
    int wm = warp >> 1, wn = warp & 1;   // GEMM-3: 4x2 grid, warp tile 32x64

    int bh = blockIdx.z;
    int b = bh / H_, h = bh % H_;
    int n0 = blockIdx.y * 68;            // {0, 68}: exact cover of 196 with 128-tiles
    int p0 = blockIdx.x * 68;

    const float* qh_b = qh + (size_t)bh * N_ * HD_;
    const float* q2_b = q2 + (size_t)bh * N_ * HD_;

    for (int idx = tid; idx < 2048; idx += 256) {
        int r = idx & 127, dq = idx >> 7;
        float4 a = *(const float4*)(qh_b + (size_t)(n0+r)*HD_ + dq*4);
        qh_s[(dq*4+0)*136 + r] = to_tf32(a.x);
        qh_s[(dq*4+1)*136 + r] = to_tf32(a.y);
        qh_s[(dq*4+2)*136 + r] = to_tf32(a.z);
        qh_s[(dq*4+3)*136 + r] = to_tf32(a.w);
        float4 u4 = *(const float4*)(q2_b + (size_t)(p0+r)*HD_ + dq*4);
        q2t[(dq*4+0)*136 + r] = to_tf32(u4.x);
        q2t[(dq*4+1)*136 + r] = to_tf32(u4.y);
        q2t[(dq*4+2)*136 + r] = to_tf32(u4.z);
        q2t[(dq*4+3)*136 + r] = to_tf32(u4.w);
    }

    float acc[2][8][4];
#pragma unroll
    for (int t = 0; t < 2; t++)
#pragma unroll
        for (int u = 0; u < 8; u++)
#pragma unroll
            for (int e = 0; e < 4; e++) acc[t][u][e] = 0.f;

    int crow = tid & 15, cdq = tid >> 4;

    for (int c = 0; c < NC_; c++) {
        float w2c = w2all[b*CH_ + h*NC_ + c];
        const float* kh_c = kh + (size_t)(c*H_ + h) * N_ * HD_;
        const float* k2_c = k2 + (size_t)(c*H_ + h) * N_ * HD_;
        for (int m0c = 0; m0c < N_; m0c += 16) {
            __syncthreads();
            {
                int m = m0c + crow;
                float4 a = make_float4(0.f,0.f,0.f,0.f), bb = make_float4(0.f,0.f,0.f,0.f);
                if (m < N_) {
                    a  = *(const float4*)(kh_c + (size_t)m*HD_ + cdq*4);
                    bb = *(const float4*)(k2_c + (size_t)m*HD_ + cdq*4);
                }
                kht[(cdq*4+0)*24 + crow] = to_tf32(a.x);
                kht[(cdq*4+1)*24 + crow] = to_tf32(a.y);
                kht[(cdq*4+2)*24 + crow] = to_tf32(a.z);
                kht[(cdq*4+3)*24 + crow] = to_tf32(a.w);
                k2t[(cdq*4+0)*24 + crow] = to_tf32(bb.x);
                k2t[(cdq*4+1)*24 + crow] = to_tf32(bb.y);
                k2t[(cdq*4+2)*24 + crow] = to_tf32(bb.z);
                k2t[(cdq*4+3)*24 + crow] = to_tf32(bb.w);
            }
            __syncthreads();
            // GEMM-1: L[n=128, m=16] = Qh_tile . Kh_chunk^T ; each warp one m16-row-block
            {
                float lacc[2][4];
#pragma unroll
                for (int u = 0; u < 2; u++)
#pragma unroll
                    for (int e = 0; e < 4; e++) lacc[u][e] = 0.f;
#pragma unroll
                for (int ks = 0; ks < 8; ks++) {
                    int k = ks*8;
                    uint32_t a0 = U32(qh_s[(k+tig)*136 + warp*16 + gid]);
                    uint32_t a1 = U32(qh_s[(k+tig)*136 + warp*16 + gid + 8]);
                    uint32_t a2 = U32(qh_s[(k+tig+4)*136 + warp*16 + gid]);
                    uint32_t a3 = U32(qh_s[(k+tig+4)*136 + warp*16 + gid + 8]);
#pragma unroll
                    for (int u = 0; u < 2; u++) {
                        uint32_t b0 = U32(kht[(k+tig)*24 + u*8 + gid]);
                        uint32_t b1 = U32(kht[(k+tig+4)*24 + u*8 + gid]);
                        mma8(lacc[u], a0,a1,a2,a3, b0,b1);
                    }
                }
#pragma unroll
                for (int u = 0; u < 2; u++) {
                    int mc = u*8 + 2*tig;
                    int nr = warp*16 + gid;
                    L_s[mc*136 + nr]         = to_tf32(w2c * fmaxf(0.f, -SCALE_*lacc[u][0]));
                    L_s[(mc+1)*136 + nr]     = to_tf32(w2c * fmaxf(0.f, -SCALE_*lacc[u][1]));
                    L_s[mc*136 + nr + 8]     = to_tf32(w2c * fmaxf(0.f, -SCALE_*lacc[u][2]));
                    L_s[(mc+1)*136 + nr + 8] = to_tf32(w2c * fmaxf(0.f, -SCALE_*lacc[u][3]));
                }
            }
            // GEMM-2: R[m=16, p=128] = K2_chunk . Q2_tile^T ; each warp a 16-col slice of p
            {
                float racc[2][4];
#pragma unroll
                for (int u = 0; u < 2; u++)
#pragma unroll
                    for (int e = 0; e < 4; e++) racc[u][e] = 0.f;
#pragma unroll
                for (int ks = 0; ks < 8; ks++) {
                    int k = ks*8;
                    uint32_t a0 = U32(k2t[(k+tig)*24 + gid]);
                    uint32_t a1 = U32(k2t[(k+tig)*24 + gid + 8]);
                    uint32_t a2 = U32(k2t[(k+tig+4)*24 + gid]);
                    uint32_t a3 = U32(k2t[(k+tig+4)*24 + gid + 8]);
#pragma unroll
                    for (int u = 0; u < 2; u++) {
                        int cb = warp*16 + u*8;
                        uint32_t b0 = U32(q2t[(k+tig)*136 + cb + gid]);
                        uint32_t b1 = U32(q2t[(k+tig+4)*136 + cb + gid]);
                        mma8(racc[u], a0,a1,a2,a3, b0,b1);
                    }
                }
#pragma unroll
                for (int u = 0; u < 2; u++) {
                    int cb = warp*16 + u*8 + 2*tig;
                    R_s[gid*136 + cb]         = to_tf32(fmaxf(0.f, SCALE_*racc[u][0]));
                    R_s[gid*136 + cb + 1]     = to_tf32(fmaxf(0.f, SCALE_*racc[u][1]));
                    R_s[(gid+8)*136 + cb]     = to_tf32(fmaxf(0.f, SCALE_*racc[u][2]));
                    R_s[(gid+8)*136 + cb + 1] = to_tf32(fmaxf(0.f, SCALE_*racc[u][3]));
                }
            }
            __syncthreads();
            // GEMM-3: acc += L . R   (K=16)
#pragma unroll
            for (int ks = 0; ks < 2; ks++) {
                int k = ks*8;
                uint32_t a[2][4];
#pragma unroll
                for (int t = 0; t < 2; t++) {
                    int mb = wm*32 + t*16;
                    a[t][0] = U32(L_s[(k+tig)*136 + mb + gid]);
                    a[t][1] = U32(L_s[(k+tig)*136 + mb + gid + 8]);
                    a[t][2] = U32(L_s[(k+tig+4)*136 + mb + gid]);
                    a[t][3] = U32(L_s[(k+tig+4)*136 + mb + gid + 8]);
                }
#pragma unroll
                for (int u = 0; u < 8; u++) {
                    int cb = wn*64 + u*8;
                    uint32_t b0 = U32(R_s[(k+tig)*136 + cb + gid]);
                    uint32_t b1 = U32(R_s[(k+tig+4)*136 + cb + gid]);
                    mma8(acc[0][u], a[0][0],a[0][1],a[0][2],a[0][3], b0,b1);
                    mma8(acc[1][u], a[1][0],a[1][1],a[1][2],a[1][3], b0,b1);
                }
            }
        }
    }

    float* o = tmp_out + (size_t)bh * N_ * N_;
#pragma unroll
    for (int t = 0; t < 2; t++) {
#pragma unroll
        for (int u = 0; u < 8; u++) {
            int n = n0 + wm*32 + t*16 + gid;
            int p = p0 + wn*64 + u*8 + 2*tig;
            o[(size_t)n*N_ + p]           = acc[t][u][0];
            o[(size_t)n*N_ + p + 1]       = acc[t][u][1];
            o[(size_t)(n+8)*N_ + p]       = acc[t][u][2];
            o[(size_t)(n+8)*N_ + p + 1]   = acc[t][u][3];
        }
    }
}

// ---------------- rect = tmp @ vr (per b,h) ----------------
__global__ __launch_bounds__(256)
void rect_kernel(const float* __restrict__ tmp, const float* __restrict__ vr,
                 float* __restrict__ rectH)
{
    extern __shared__ float sm[];
    float* vr_s  = sm;            // [196][64]
    float* tmp_s = sm + N_*HD_;   // [4][196]
    int bh = blockIdx.y;
    int r0 = blockIdx.x * 4;
    const float* vrb = vr + (size_t)bh * N_ * HD_;
    for (int i = threadIdx.x; i < N_*HD_/4; i += 256)
        ((float4*)vr_s)[i] = ((const float4*)vrb)[i];
    const float* tb = tmp + (size_t)bh * N_ * N_;
    for (int i = threadIdx.x; i < 4*N_; i += 256) {
        int rr = i / N_, kk = i % N_;
        tmp_s[i] = tb[(size_t)(r0 + rr)*N_ + kk];
    }
    __syncthreads();
    int d = threadIdx.x & 63, rr = threadIdx.x >> 6;
    float a = 0.f;
    for (int kk = 0; kk < N_; kk++) a += tmp_s[rr*N_ + kk] * vr_s[kk*HD_ + d];
    rectH[(size_t)bh*N_*HD_ + (size_t)(r0 + rr)*HD_ + d] = a;
}

// ---------------- anchor copy ----------------
__global__ void copy_kernel(const float* __restrict__ src, float* __restrict__ dst, int n4)
{
    int i = blockIdx.x * blockDim.x + threadIdx.x;
    if (i < n4) ((float4*)dst)[i] = ((const float4*)src)[i];
}

// ---------------- launch ----------------
extern "C" void kernel_launch(void* const* d_in, const int* in_sizes, int n_in,
                              void* d_out, int out_size)
{
    const float* x       = (const float*)d_in[0];
    const float* Wqv     = (const float*)d_in[1];
    const float* Wk      = (const float*)d_in[2];
    const float* Wq_proj = (const float*)d_in[3];
    const float* bq_proj = (const float*)d_in[4];
    const float* Wqk     = (const float*)d_in[5];
    const float* Wqk2    = (const float*)d_in[6];
    const float* Wv      = (const float*)d_in[7];
    const float* Wr_proj = (const float*)d_in[8];
    const float* br_proj = (const float*)d_in[9];
    const float* g1      = (const float*)d_in[10];
    const float* b1      = (const float*)d_in[11];
    const float* g2      = (const float*)d_in[12];
    const float* b2      = (const float*)d_in[13];
    const float* g3      = (const float*)d_in[14];
    const float* b3      = (const float*)d_in[15];
    const float* W1      = (const float*)d_in[16];
    const float* bm1     = (const float*)d_in[17];
    const float* W2      = (const float*)d_in[18];
    const float* bm2     = (const float*)d_in[19];
    float* outp = (float*)d_out;

    float *n1, *n2x, *n2a, *qv, *kb, *attn, *ctx, *qh, *q2, *vrp, *khp, *k2p;
    float *tmp, *rectH, *xx, *hdn, *h1;
    cudaGetSymbolAddress((void**)&n1, g_n1);
    cudaGetSymbolAddress((void**)&n2x, g_n2x);
    cudaGetSymbolAddress((void**)&n2a, g_n2a);
    cudaGetSymbolAddress((void**)&qv, g_qv);
    cudaGetSymbolAddress((void**)&kb, g_k);
    cudaGetSymbolAddress((void**)&attn, g_attn);
    cudaGetSymbolAddress((void**)&ctx, g_ctx);
    cudaGetSymbolAddress((void**)&qh, g_qh);
    cudaGetSymbolAddress((void**)&q2, g_q2);
    cudaGetSymbolAddress((void**)&vrp, g_vr);
    cudaGetSymbolAddress((void**)&khp, g_kh);
    cudaGetSymbolAddress((void**)&k2p, g_k2);
    cudaGetSymbolAddress((void**)&tmp, g_tmp);
    cudaGetSymbolAddress((void**)&rectH, g_rectH);
    cudaGetSymbolAddress((void**)&xx, g_xx);
    cudaGetSymbolAddress((void**)&hdn, g_hdn);
    cudaGetSymbolAddress((void**)&h1, g_h1);

    const int SMEM_F = 24832 * 4;
    const int SMEM_R = (N_*HD_ + 4*N_) * 4;
    cudaFuncSetAttribute(fused_attn_tf32, cudaFuncAttributeMaxDynamicSharedMemorySize, SMEM_F);
    cudaFuncSetAttribute(rect_kernel, cudaFuncAttributeMaxDynamicSharedMemorySize, SMEM_R);

    // 1) LayerNorms
    ln_kernel<<<26, 128>>>(x, n1, g1, b1, 26, 26, 0, (long)T_*C_);
    ln_kernel<<<B_*N_, 128>>>(x + C_, n2x, g2, b2, B_*N_, N_, (long)T_*C_, C_);
    ln_kernel<<<NC_*N_, 128>>>(x + (long)16*T_*C_ + C_, n2a, g2, b2, NC_*N_, N_, (long)T_*C_, C_);

    // 2) cls path: qv = n1a@Wqv, k = n1x@Wk (tensor-core GEMMs)
    gemm_tf32<<<dim3(12,1), 256>>>(n1 + 16*C_, Wqv, nullptr, nullptr, qv, NC_, 2*C_, C_, 0, 0);
    gemm_tf32<<<dim3(6,1), 256>>>(n1, Wk, nullptr, nullptr, kb, B_, C_, C_, 0, 0);
    attn_cls_kernel<<<B_, 384>>>(qv, kb, attn, ctx);
    gemm_tf32<<<dim3(6,1), 256>>>(ctx, Wq_proj, bq_proj, nullptr, xx, B_, C_, C_, 0, 3);

    // 3) head projections (head-major outputs)
    dim3 gx(6, 25), ga(6, 16);
    gemm_tf32<<<gx, 256>>>(n2x, Wqk,  nullptr, nullptr, qh,  B_*N_, C_, C_, 0, 1);
    gemm_tf32<<<gx, 256>>>(n2x, Wqk2, nullptr, nullptr, q2,  B_*N_, C_, C_, 0, 1);
    gemm_tf32<<<gx, 256>>>(n2x, Wv,   nullptr, nullptr, vrp, B_*N_, C_, C_, 0, 1);
    gemm_tf32<<<ga, 256>>>(n2a, Wqk,  nullptr, nullptr, khp, NC_*N_, C_, C_, 0, 1);
    gemm_tf32<<<ga, 256>>>(n2a, Wqk2, nullptr, nullptr, k2p, NC_*N_, C_, C_, 0, 1);

    // 4) fused rectified attention core (tensor cores)
    dim3 gf(2, 2, BH_);
    fused_attn_tf32<<<gf, 256, SMEM_F>>>(qh, khp, q2, k2p, attn, tmp);

    // 5) rect = tmp @ vr
    dim3 gr(49, BH_);
    rect_kernel<<<gr, 256, SMEM_R>>>(tmp, vrp, rectH);

    // 6) rect projection + residual -> xx rows 1..196
    gemm_tf32<<<gx, 256>>>(rectH, Wr_proj, br_proj, x, xx, B_*N_, C_, C_, 0, 2);

    // 7) MLP
    ln_kernel<<<B_*T_, 128>>>(xx, hdn, g3, b3, B_*T_, B_*T_, 0, C_);
    dim3 gm1(24, 25), gm2(6, 25);
    gemm_tf32<<<gm1, 256>>>(hdn, W1, bm1, nullptr, h1, B_*T_, 4*C_, C_, 1, 0);
    gemm_tf32<<<gm2, 256>>>(h1, W2, bm2, xx, outp, B_*T_, C_, 4*C_, 0, 0);

    // 8) anchors pass-through
    int n4 = NC_*T_*C_/4;
    copy_kernel<<<(n4 + 255)/256, 256>>>(x + (long)16*T_*C_, outp + (long)16*T_*C_, n4);
}